// round 9
// baseline (speedup 1.0000x reference)
#include <cuda_runtime.h>
#include <cuda_bf16.h>
#include <cstdint>

// Problem constants
#define N        8192
#define IN_DIM   512
#define NCLASS   16
#define PC       512      // per class
#define KK       256      // kept per class
#define NSEL     4096     // NCLASS * KK

// Output layout (single f32 buffer): M_out | X_out | mask_out
#define M_OUT_OFF    0
#define X_OUT_OFF    (NSEL * (size_t)NSEL)               // 16777216
#define MASK_OUT_OFF (X_OUT_OFF + NSEL * (size_t)IN_DIM) // 18874368

// Scratch (device globals — no allocation allowed)
__device__ int                g_idx[NSEL];
__device__ float              g_vals[NSEL];
__device__ unsigned           g_cnt[NCLASS];   // monotone; pos = old & 511
__device__ unsigned long long g_keys[N];

// ---------------------------------------------------------------------------
// Bit-replica of XLA:CPU / Eigen Cephes expf (confirmed bit-exact: R5 w=0).
// ---------------------------------------------------------------------------
__device__ __forceinline__ float cephes_expf(float r) {
    float in = fminf(fmaxf(r, -88.3762626647949f), 88.3762626647950f);
    float fx = floorf(__fmaf_rn(in, 1.44269504088896341f, 0.5f));
    float tmp = __fmul_rn(0.693359375f, fx);
    float zz  = __fmul_rn(-2.12194440e-4f, fx);
    float x   = __fsub_rn(__fsub_rn(in, tmp), zz);
    float z2  = __fmul_rn(x, x);
    float y   = __fmaf_rn(x, 1.9875691500E-4f, 1.3981999507E-3f);
    y = __fmaf_rn(y, x, 8.3334519073E-3f);
    y = __fmaf_rn(y, x, 4.1665795894E-2f);
    y = __fmaf_rn(y, x, 1.6666665459E-1f);
    y = __fmaf_rn(y, x, 5.0000001201E-1f);
    y = __fmaf_rn(y, z2, x);
    y = __fadd_rn(1.0f, y);
    int n = (int)fx;
    float pow2n = __int_as_float((unsigned)(n + 127) << 23);
    return __fmul_rn(y, pow2n);
}

// ---------------------------------------------------------------------------
// Kernel 1 (fused detect + score + scatter), one warp per row (8 rows/block).
// Vectorized: each lane holds 4 float4 of X and W (8 independent 16B loads
// in flight -> MLP ~8) with 8 separate FMA accumulators. Reduction order is
// irrelevant at score precision (established R1==R4); only the Cephes
// sigmoid must be bit-exact.
// ---------------------------------------------------------------------------
__global__ void score_kernel(const float* __restrict__ X,
                             const float* __restrict__ W,
                             const float* __restrict__ b,
                             const int* __restrict__ mask_i32) {
    __shared__ unsigned warp_any[8];
    __shared__ int s_is64;

    const int t    = threadIdx.x;          // 0..255
    const int wid  = t >> 5;
    const int lane = t & 31;

    // --- embedded is64 detection (first 128 odd int32 words all zero?) ---
    int nz = (mask_i32[2 * (t & 127) + 1] != 0);
    unsigned any = __ballot_sync(0xffffffffu, nz);
    if (lane == 0) warp_any[wid] = any;
    __syncthreads();
    if (t == 0) {
        unsigned a = 0;
#pragma unroll
        for (int w = 0; w < 8; ++w) a |= warp_any[w];
        s_is64 = (a == 0u) ? 1 : 0;
    }
    __syncthreads();
    const int is64 = s_is64;

    // --- vectorized dot: row has 128 float4s; lane gets 4 of them ---
    const int row = blockIdx.x * 8 + wid;
    const float4* xr4 = (const float4*)(X + (size_t)row * IN_DIM);
    const float4* w4  = (const float4*)W;

    float4 x0 = xr4[lane +  0], x1 = xr4[lane + 32],
           x2 = xr4[lane + 64], x3 = xr4[lane + 96];
    float4 q0 = __ldg(&w4[lane +  0]), q1 = __ldg(&w4[lane + 32]),
           q2 = __ldg(&w4[lane + 64]), q3 = __ldg(&w4[lane + 96]);

    float a0 = __fmul_rn(x0.x, q0.x), a1 = __fmul_rn(x0.y, q0.y);
    float a2 = __fmul_rn(x0.z, q0.z), a3 = __fmul_rn(x0.w, q0.w);
    float a4 = __fmul_rn(x1.x, q1.x), a5 = __fmul_rn(x1.y, q1.y);
    float a6 = __fmul_rn(x1.z, q1.z), a7 = __fmul_rn(x1.w, q1.w);
    a0 = __fmaf_rn(x2.x, q2.x, a0);  a1 = __fmaf_rn(x2.y, q2.y, a1);
    a2 = __fmaf_rn(x2.z, q2.z, a2);  a3 = __fmaf_rn(x2.w, q2.w, a3);
    a4 = __fmaf_rn(x3.x, q3.x, a4);  a5 = __fmaf_rn(x3.y, q3.y, a5);
    a6 = __fmaf_rn(x3.z, q3.z, a6);  a7 = __fmaf_rn(x3.w, q3.w, a7);

    float s = __fadd_rn(__fadd_rn(__fadd_rn(a0, a1), __fadd_rn(a2, a3)),
                        __fadd_rn(__fadd_rn(a4, a5), __fadd_rn(a6, a7)));
#pragma unroll
    for (int o = 16; o > 0; o >>= 1)
        s += __shfl_xor_sync(0xffffffffu, s, o);

    if (lane == 0) {
        float x  = __fdiv_rn(__fadd_rn(s, b[0]), 100.0f);
        float tt = cephes_expf(-x);
        float sc = __fdiv_rn(1.0f, __fadd_rn(1.0f, tt));
        unsigned sb = __float_as_uint(sc);          // (0,1): bit order == value order
        int cls = is64 ? mask_i32[2 * row] : mask_i32[row];
        unsigned pos = atomicAdd(&g_cnt[cls], 1u) & (PC - 1);
        g_keys[cls * PC + pos] = ((unsigned long long)sb << 32) | (unsigned)row;
    }
}

// ---------------------------------------------------------------------------
// Hybrid bitonic sort, 512 keys/class, one block (512 thr) per class.
// Intra-warp spans via shfl_xor (no barriers); 10 cross-warp stages in SMEM.
// ---------------------------------------------------------------------------
__device__ __forceinline__ unsigned long long cex_shfl(unsigned long long v,
                                                       int s, bool asc, int e) {
    unsigned long long o = __shfl_xor_sync(0xffffffffu, v, s);
    bool lower   = (e & s) == 0;
    bool keepMin = (lower == asc);
    return keepMin ? (o < v ? o : v) : (o > v ? o : v);
}

__global__ __launch_bounds__(PC) void sort_kernel(float* __restrict__ out) {
    __shared__ unsigned long long keys[PC];
    const int j   = blockIdx.x;
    const int tid = threadIdx.x;

    unsigned long long v = g_keys[j * PC + tid];

#pragma unroll
    for (unsigned k = 2; k <= 32; k <<= 1) {
        bool asc = ((tid & k) == 0);
        for (int s = k >> 1; s >= 1; s >>= 1)
            v = cex_shfl(v, s, asc, tid);
    }
    keys[tid] = v;

#pragma unroll
    for (unsigned k = 64; k <= PC; k <<= 1) {
        for (unsigned s = k >> 1; s >= 32; s >>= 1) {
            __syncthreads();
            unsigned partner = tid ^ s;
            if (partner > (unsigned)tid) {
                unsigned long long a  = keys[tid];
                unsigned long long bb = keys[partner];
                bool ascending = ((tid & k) == 0);
                if ((a > bb) == ascending) {
                    keys[tid]     = bb;
                    keys[partner] = a;
                }
            }
        }
        __syncthreads();
        v = keys[tid];
        bool asc = ((tid & k) == 0);
#pragma unroll
        for (int s = 16; s >= 1; s >>= 1)
            v = cex_shfl(v, s, asc, tid);
        keys[tid] = v;
    }

    if (tid < KK) {
        int o = j * KK + tid;
        g_idx[o]  = (int)(unsigned)(v & 0xffffffffu);
        g_vals[o] = __uint_as_float((unsigned)(v >> 32));
        out[MASK_OUT_OFF + o] = (float)j;   // mask[idx] == class id by construction
    }
}

// ---------------------------------------------------------------------------
// cp.async helpers
// ---------------------------------------------------------------------------
__device__ __forceinline__ void cp_async16(uint32_t saddr, const void* gptr) {
    asm volatile("cp.async.cg.shared.global [%0], [%1], 16;\n"
                 :: "r"(saddr), "l"(gptr));
}
__device__ __forceinline__ void cp_commit() {
    asm volatile("cp.async.commit_group;\n");
}
template <int NN>
__device__ __forceinline__ void cp_wait() {
    asm volatile("cp.async.wait_group %0;\n" :: "n"(NN));
}

// ---------------------------------------------------------------------------
// Kernel 3 (fused, pipelined): 4 output rows per block, double-buffered
// cp.async row staging so row k+1's DRAM loads overlap row k's gather.
//   X_out[r,:] = X[idx[r],:] * vals[r]
//   M_out[r,c] = M[idx[r], idx[c]]
// 512 threads; dynamic SMEM = 2 * 32KB.
// ---------------------------------------------------------------------------
#define MROWS 4
extern __shared__ float s_buf[];   // [2][N]

__device__ __forceinline__ void issue_row(const float* __restrict__ M,
                                          int ri, int bufsel) {
    uint32_t sbase = (uint32_t)__cvta_generic_to_shared(&s_buf[bufsel * N]);
    const char* g = (const char*)(M + (size_t)ri * N);
    int t = threadIdx.x;
#pragma unroll
    for (int i = 0; i < 4; ++i) {
        int off16 = (t + i * 512) * 16;
        cp_async16(sbase + off16, g + off16);
    }
    cp_commit();
}

__device__ __forceinline__ void gather_row(float* __restrict__ out,
                                           int r, int bufsel) {
    const float* row = &s_buf[bufsel * N];
    float4* dst4 = (float4*)(out + M_OUT_OFF + (size_t)r * NSEL);
    const int4* gi4 = (const int4*)g_idx;
#pragma unroll
    for (int i = 0; i < 2; ++i) {
        int t = threadIdx.x + i * 512;
        int4 ii = gi4[t];
        float4 o;
        o.x = row[ii.x];
        o.y = row[ii.y];
        o.z = row[ii.z];
        o.w = row[ii.w];
        dst4[t] = o;
    }
}

__global__ __launch_bounds__(512) void moutx_kernel(const float* __restrict__ M,
                                                    const float* __restrict__ X,
                                                    float* __restrict__ out) {
    const int r0 = blockIdx.x * MROWS;
    const int t  = threadIdx.x;

    int ri1 = g_idx[r0 + 1];
    int ri2 = g_idx[r0 + 2];
    int ri3 = g_idx[r0 + 3];

    issue_row(M, g_idx[r0 + 0], 0);    // group 0
    issue_row(M, ri1, 1);              // group 1

    // X rows (one float4 per thread covers all 4 rows), overlaps the loads
    {
        int xr  = t >> 7;              // 0..3
        int col = t & 127;
        int r   = r0 + xr;
        float v = g_vals[r];
        float4 x = ((const float4*)(X + (size_t)g_idx[r] * IN_DIM))[col];
        ((float4*)(out + X_OUT_OFF + (size_t)r * IN_DIM))[col] =
            make_float4(x.x * v, x.y * v, x.z * v, x.w * v);
    }

    cp_wait<1>(); __syncthreads();
    gather_row(out, r0 + 0, 0);
    __syncthreads();
    issue_row(M, ri2, 0);              // group 2

    cp_wait<1>(); __syncthreads();
    gather_row(out, r0 + 1, 1);
    __syncthreads();
    issue_row(M, ri3, 1);              // group 3

    cp_wait<1>(); __syncthreads();
    gather_row(out, r0 + 2, 0);

    cp_wait<0>(); __syncthreads();
    gather_row(out, r0 + 3, 1);
}

// ---------------------------------------------------------------------------
extern "C" void kernel_launch(void* const* d_in, const int* in_sizes, int n_in,
                              void* d_out, int out_size) {
    const float* M    = (const float*)d_in[0];
    const float* X    = (const float*)d_in[1];
    const int*   mask = (const int*)  d_in[2];
    const float* W    = (const float*)d_in[3];
    const float* b    = (const float*)d_in[4];
    float* out = (float*)d_out;

    static const size_t MOUT_SMEM = 2 * N * sizeof(float);   // 64 KB
    cudaFuncSetAttribute(moutx_kernel,
                         cudaFuncAttributeMaxDynamicSharedMemorySize,
                         (int)MOUT_SMEM);

    score_kernel<<<N / 8, 256>>>(X, W, b, mask);
    sort_kernel<<<NCLASS, PC>>>(out);
    moutx_kernel<<<NSEL / MROWS, 512, MOUT_SMEM>>>(M, X, out);
}

// round 10
// speedup vs baseline: 1.0748x; 1.0748x over previous
#include <cuda_runtime.h>
#include <cuda_bf16.h>
#include <cstdint>

// Problem constants
#define N        8192
#define IN_DIM   512
#define NCLASS   16
#define PC       512      // per class
#define KK       256      // kept per class
#define NSEL     4096     // NCLASS * KK

// Output layout (single f32 buffer): M_out | X_out | mask_out
#define M_OUT_OFF    0
#define X_OUT_OFF    (NSEL * (size_t)NSEL)               // 16777216
#define MASK_OUT_OFF (X_OUT_OFF + NSEL * (size_t)IN_DIM) // 18874368

// Scratch (device globals — no allocation allowed)
// Counters padded to 256B stride so each class lands in its own L2 slice
// (16 counters in one line would serialize all 8192 atomics through one LTS).
#define CNT_STRIDE 64
__device__ int                g_idx[NSEL];
__device__ float              g_vals[NSEL];
__device__ unsigned           g_cnt[NCLASS * CNT_STRIDE];   // monotone; pos = old & 511
__device__ unsigned long long g_keys[N];

// ---------------------------------------------------------------------------
// Bit-replica of XLA:CPU / Eigen Cephes expf (confirmed bit-exact: R5 w=0).
// ---------------------------------------------------------------------------
__device__ __forceinline__ float cephes_expf(float r) {
    float in = fminf(fmaxf(r, -88.3762626647949f), 88.3762626647950f);
    float fx = floorf(__fmaf_rn(in, 1.44269504088896341f, 0.5f));
    float tmp = __fmul_rn(0.693359375f, fx);
    float zz  = __fmul_rn(-2.12194440e-4f, fx);
    float x   = __fsub_rn(__fsub_rn(in, tmp), zz);
    float z2  = __fmul_rn(x, x);
    float y   = __fmaf_rn(x, 1.9875691500E-4f, 1.3981999507E-3f);
    y = __fmaf_rn(y, x, 8.3334519073E-3f);
    y = __fmaf_rn(y, x, 4.1665795894E-2f);
    y = __fmaf_rn(y, x, 1.6666665459E-1f);
    y = __fmaf_rn(y, x, 5.0000001201E-1f);
    y = __fmaf_rn(y, z2, x);
    y = __fadd_rn(1.0f, y);
    int n = (int)fx;
    float pow2n = __int_as_float((unsigned)(n + 127) << 23);
    return __fmul_rn(y, pow2n);
}

// ---------------------------------------------------------------------------
// Kernel 1 (fused detect + score + scatter), one warp per row (8 rows/block).
// Vectorized float4 dot (8 independent 16B loads, 8 accumulators). Reduction
// order is irrelevant at score precision (established); only the Cephes
// sigmoid must be bit-exact. Scatter atomics hit 256B-strided counters.
// ---------------------------------------------------------------------------
__global__ void score_kernel(const float* __restrict__ X,
                             const float* __restrict__ W,
                             const float* __restrict__ b,
                             const int* __restrict__ mask_i32) {
    __shared__ unsigned warp_any[8];
    __shared__ int s_is64;

    const int t    = threadIdx.x;          // 0..255
    const int wid  = t >> 5;
    const int lane = t & 31;

    // --- vectorized dot first (loads issue before any barrier) ---
    const int row = blockIdx.x * 8 + wid;
    const float4* xr4 = (const float4*)(X + (size_t)row * IN_DIM);
    const float4* w4  = (const float4*)W;

    float4 x0 = xr4[lane +  0], x1 = xr4[lane + 32],
           x2 = xr4[lane + 64], x3 = xr4[lane + 96];
    float4 q0 = __ldg(&w4[lane +  0]), q1 = __ldg(&w4[lane + 32]),
           q2 = __ldg(&w4[lane + 64]), q3 = __ldg(&w4[lane + 96]);

    // --- embedded is64 detection (first 128 odd int32 words all zero?) ---
    int nz = (mask_i32[2 * (t & 127) + 1] != 0);
    unsigned any = __ballot_sync(0xffffffffu, nz);
    if (lane == 0) warp_any[wid] = any;

    float a0 = __fmul_rn(x0.x, q0.x), a1 = __fmul_rn(x0.y, q0.y);
    float a2 = __fmul_rn(x0.z, q0.z), a3 = __fmul_rn(x0.w, q0.w);
    float a4 = __fmul_rn(x1.x, q1.x), a5 = __fmul_rn(x1.y, q1.y);
    float a6 = __fmul_rn(x1.z, q1.z), a7 = __fmul_rn(x1.w, q1.w);
    a0 = __fmaf_rn(x2.x, q2.x, a0);  a1 = __fmaf_rn(x2.y, q2.y, a1);
    a2 = __fmaf_rn(x2.z, q2.z, a2);  a3 = __fmaf_rn(x2.w, q2.w, a3);
    a4 = __fmaf_rn(x3.x, q3.x, a4);  a5 = __fmaf_rn(x3.y, q3.y, a5);
    a6 = __fmaf_rn(x3.z, q3.z, a6);  a7 = __fmaf_rn(x3.w, q3.w, a7);

    float s = __fadd_rn(__fadd_rn(__fadd_rn(a0, a1), __fadd_rn(a2, a3)),
                        __fadd_rn(__fadd_rn(a4, a5), __fadd_rn(a6, a7)));
#pragma unroll
    for (int o = 16; o > 0; o >>= 1)
        s += __shfl_xor_sync(0xffffffffu, s, o);

    __syncthreads();
    if (t == 0) {
        unsigned a = 0;
#pragma unroll
        for (int w = 0; w < 8; ++w) a |= warp_any[w];
        s_is64 = (a == 0u) ? 1 : 0;
    }
    __syncthreads();
    const int is64 = s_is64;

    if (lane == 0) {
        float x  = __fdiv_rn(__fadd_rn(s, b[0]), 100.0f);
        float tt = cephes_expf(-x);
        float sc = __fdiv_rn(1.0f, __fadd_rn(1.0f, tt));
        unsigned sb = __float_as_uint(sc);          // (0,1): bit order == value order
        int cls = is64 ? mask_i32[2 * row] : mask_i32[row];
        unsigned pos = atomicAdd(&g_cnt[cls * CNT_STRIDE], 1u) & (PC - 1);
        g_keys[cls * PC + pos] = ((unsigned long long)sb << 32) | (unsigned)row;
    }
}

// ---------------------------------------------------------------------------
// Hybrid bitonic sort, 512 keys/class, one block (512 thr) per class.
// Intra-warp spans via shfl_xor (no barriers); 10 cross-warp stages in SMEM.
// ---------------------------------------------------------------------------
__device__ __forceinline__ unsigned long long cex_shfl(unsigned long long v,
                                                       int s, bool asc, int e) {
    unsigned long long o = __shfl_xor_sync(0xffffffffu, v, s);
    bool lower   = (e & s) == 0;
    bool keepMin = (lower == asc);
    return keepMin ? (o < v ? o : v) : (o > v ? o : v);
}

__global__ __launch_bounds__(PC) void sort_kernel(float* __restrict__ out) {
    __shared__ unsigned long long keys[PC];
    const int j   = blockIdx.x;
    const int tid = threadIdx.x;

    unsigned long long v = g_keys[j * PC + tid];

#pragma unroll
    for (unsigned k = 2; k <= 32; k <<= 1) {
        bool asc = ((tid & k) == 0);
        for (int s = k >> 1; s >= 1; s >>= 1)
            v = cex_shfl(v, s, asc, tid);
    }
    keys[tid] = v;

#pragma unroll
    for (unsigned k = 64; k <= PC; k <<= 1) {
        for (unsigned s = k >> 1; s >= 32; s >>= 1) {
            __syncthreads();
            unsigned partner = tid ^ s;
            if (partner > (unsigned)tid) {
                unsigned long long a  = keys[tid];
                unsigned long long bb = keys[partner];
                bool ascending = ((tid & k) == 0);
                if ((a > bb) == ascending) {
                    keys[tid]     = bb;
                    keys[partner] = a;
                }
            }
        }
        __syncthreads();
        v = keys[tid];
        bool asc = ((tid & k) == 0);
#pragma unroll
        for (int s = 16; s >= 1; s >>= 1)
            v = cex_shfl(v, s, asc, tid);
        keys[tid] = v;
    }

    if (tid < KK) {
        int o = j * KK + tid;
        g_idx[o]  = (int)(unsigned)(v & 0xffffffffu);
        g_vals[o] = __uint_as_float((unsigned)(v >> 32));
        out[MASK_OUT_OFF + o] = (float)j;   // mask[idx] == class id by construction
    }
}

// ---------------------------------------------------------------------------
// cp.async helpers
// ---------------------------------------------------------------------------
__device__ __forceinline__ void cp_async16(uint32_t saddr, const void* gptr) {
    asm volatile("cp.async.cg.shared.global [%0], [%1], 16;\n"
                 :: "r"(saddr), "l"(gptr));
}
__device__ __forceinline__ void cp_commit() {
    asm volatile("cp.async.commit_group;\n");
}
template <int NN>
__device__ __forceinline__ void cp_wait() {
    asm volatile("cp.async.wait_group %0;\n" :: "n"(NN));
}

// ---------------------------------------------------------------------------
// Kernel 3 (fused, pipelined): 4 output rows per block, double-buffered
// cp.async row staging so row k+1's DRAM loads overlap row k's gather.
//   X_out[r,:] = X[idx[r],:] * vals[r]
//   M_out[r,c] = M[idx[r], idx[c]]
// 512 threads; dynamic SMEM = 2 * 32KB.
// ---------------------------------------------------------------------------
#define MROWS 4
extern __shared__ float s_buf[];   // [2][N]

__device__ __forceinline__ void issue_row(const float* __restrict__ M,
                                          int ri, int bufsel) {
    uint32_t sbase = (uint32_t)__cvta_generic_to_shared(&s_buf[bufsel * N]);
    const char* g = (const char*)(M + (size_t)ri * N);
    int t = threadIdx.x;
#pragma unroll
    for (int i = 0; i < 4; ++i) {
        int off16 = (t + i * 512) * 16;
        cp_async16(sbase + off16, g + off16);
    }
    cp_commit();
}

__device__ __forceinline__ void gather_row(float* __restrict__ out,
                                           int r, int bufsel) {
    const float* row = &s_buf[bufsel * N];
    float4* dst4 = (float4*)(out + M_OUT_OFF + (size_t)r * NSEL);
    const int4* gi4 = (const int4*)g_idx;
#pragma unroll
    for (int i = 0; i < 2; ++i) {
        int t = threadIdx.x + i * 512;
        int4 ii = gi4[t];
        float4 o;
        o.x = row[ii.x];
        o.y = row[ii.y];
        o.z = row[ii.z];
        o.w = row[ii.w];
        dst4[t] = o;
    }
}

__global__ __launch_bounds__(512) void moutx_kernel(const float* __restrict__ M,
                                                    const float* __restrict__ X,
                                                    float* __restrict__ out) {
    const int r0 = blockIdx.x * MROWS;
    const int t  = threadIdx.x;

    int ri1 = g_idx[r0 + 1];
    int ri2 = g_idx[r0 + 2];
    int ri3 = g_idx[r0 + 3];

    issue_row(M, g_idx[r0 + 0], 0);    // group 0
    issue_row(M, ri1, 1);              // group 1

    // X rows (one float4 per thread covers all 4 rows), overlaps the loads
    {
        int xr  = t >> 7;              // 0..3
        int col = t & 127;
        int r   = r0 + xr;
        float v = g_vals[r];
        float4 x = ((const float4*)(X + (size_t)g_idx[r] * IN_DIM))[col];
        ((float4*)(out + X_OUT_OFF + (size_t)r * IN_DIM))[col] =
            make_float4(x.x * v, x.y * v, x.z * v, x.w * v);
    }

    cp_wait<1>(); __syncthreads();
    gather_row(out, r0 + 0, 0);
    __syncthreads();
    issue_row(M, ri2, 0);              // group 2

    cp_wait<1>(); __syncthreads();
    gather_row(out, r0 + 1, 1);
    __syncthreads();
    issue_row(M, ri3, 1);              // group 3

    cp_wait<1>(); __syncthreads();
    gather_row(out, r0 + 2, 0);

    cp_wait<0>(); __syncthreads();
    gather_row(out, r0 + 3, 1);
}

// ---------------------------------------------------------------------------
extern "C" void kernel_launch(void* const* d_in, const int* in_sizes, int n_in,
                              void* d_out, int out_size) {
    const float* M    = (const float*)d_in[0];
    const float* X    = (const float*)d_in[1];
    const int*   mask = (const int*)  d_in[2];
    const float* W    = (const float*)d_in[3];
    const float* b    = (const float*)d_in[4];
    float* out = (float*)d_out;

    static const size_t MOUT_SMEM = 2 * N * sizeof(float);   // 64 KB
    cudaFuncSetAttribute(moutx_kernel,
                         cudaFuncAttributeMaxDynamicSharedMemorySize,
                         (int)MOUT_SMEM);

    score_kernel<<<N / 8, 256>>>(X, W, b, mask);
    sort_kernel<<<NCLASS, PC>>>(out);
    moutx_kernel<<<NSEL / MROWS, 512, MOUT_SMEM>>>(M, X, out);
}